// round 8
// baseline (speedup 1.0000x reference)
#include <cuda_runtime.h>
#include <cuda_fp16.h>

#define N_NODES 50000
#define N_EDGES 1600000
#define IN_DIM 128
#define OUT_DIM 32
#define HEADS 4
#define HD 128           // HEADS * OUT_DIM
#define EDGE_DIM 16

// ---------------- device scratch (static: no allocation allowed) ----------------
// g_cnt invariant: all-zero at kernel_launch entry. First call: .bss zero-init.
// Every call: k_edge re-zeroes it (after k_scan consumed it, before next call's k_hist).
__device__ __half g_hh[N_NODES * HD];         // 12.8 MB  h (fp16)
__device__ float g_asrc[N_NODES * HEADS];
__device__ float g_adst[N_NODES * HEADS];
__device__ int   g_cnt[N_NODES];
__device__ int   g_off[N_NODES + 1];
__device__ int   g_rank[N_EDGES];             // rank of edge within its dst segment
__device__ int   g_csr_src[N_EDGES];          // 6.4 MB
__device__ uint2 g_csr_exp[N_EDGES];          // 12.8 MB: 4 x fp16 exp(logit) per edge

// ---------------- hist: 4 edges/thread for MLP ----------------
__global__ void k_hist(const int* __restrict__ ei) {
    int i = blockIdx.x * blockDim.x + threadIdx.x;
    if (i < N_EDGES / 4) {
        int4 d4 = ((const int4*)(ei + N_EDGES))[i];
        int4 r;
        r.x = atomicAdd(&g_cnt[d4.x], 1);
        r.y = atomicAdd(&g_cnt[d4.y], 1);
        r.z = atomicAdd(&g_cnt[d4.z], 1);
        r.w = atomicAdd(&g_cnt[d4.w], 1);
        ((int4*)g_rank)[i] = r;
    }
}

// ---------------- GEMM: h = x@W^T, 128x128 tile, 256 thr, 8x8/thread (fmaf) ----------------
// W read directly from global in transposed order (64KB, cache-resident after warmup).
__global__ __launch_bounds__(256) void k_gemm(const float* __restrict__ x,
                                              const float* __restrict__ W,
                                              const float* __restrict__ att_src,
                                              const float* __restrict__ att_dst) {
    __shared__ float ws[32][136];   // W chunk [kk][j], padded
    __shared__ float xs[128][33];   // x chunk [n][kk], padded

    int tid = threadIdx.x;
    int tx = tid & 15;      // cols tx*8 .. tx*8+7
    int ty = tid >> 4;      // nodes ty*8 .. ty*8+7
    int n0 = blockIdx.x * 128;

    float avs[8], avd[8];
    {
        float4 s0 = __ldg((const float4*)&att_src[tx * 8]);
        float4 s1 = __ldg((const float4*)&att_src[tx * 8 + 4]);
        float4 d0 = __ldg((const float4*)&att_dst[tx * 8]);
        float4 d1 = __ldg((const float4*)&att_dst[tx * 8 + 4]);
        avs[0]=s0.x; avs[1]=s0.y; avs[2]=s0.z; avs[3]=s0.w;
        avs[4]=s1.x; avs[5]=s1.y; avs[6]=s1.z; avs[7]=s1.w;
        avd[0]=d0.x; avd[1]=d0.y; avd[2]=d0.z; avd[3]=d0.w;
        avd[4]=d1.x; avd[5]=d1.y; avd[6]=d1.z; avd[7]=d1.w;
    }

    float acc[8][8];
#pragma unroll
    for (int i = 0; i < 8; i++)
#pragma unroll
        for (int j = 0; j < 8; j++) acc[i][j] = 0.f;

    for (int kc = 0; kc < IN_DIM; kc += 32) {
        __syncthreads();
        // W chunk: ws[kk][j] = W[j][kc+kk]; smem stores conflict-free, global reads cached
        for (int i = tid; i < 32 * HD; i += 256) {
            int kk = i >> 7, j = i & 127;
            ws[kk][j] = W[j * IN_DIM + kc + kk];
        }
        // x chunk: 128 nodes x 32 k, coalesced
        for (int i = tid; i < 128 * 32; i += 256) {
            int nn = i >> 5, kk = i & 31;
            int gn = n0 + nn;
            xs[nn][kk] = (gn < N_NODES) ? x[gn * IN_DIM + kc + kk] : 0.f;
        }
        __syncthreads();

#pragma unroll 4
        for (int kk = 0; kk < 32; kk++) {
            float4 w0 = *(const float4*)&ws[kk][tx * 8];
            float4 w1 = *(const float4*)&ws[kk][tx * 8 + 4];
            float wv[8] = {w0.x, w0.y, w0.z, w0.w, w1.x, w1.y, w1.z, w1.w};
            float xv[8];
#pragma unroll
            for (int i = 0; i < 8; i++) xv[i] = xs[ty * 8 + i][kk];
#pragma unroll
            for (int i = 0; i < 8; i++)
#pragma unroll
                for (int j = 0; j < 8; j++)
                    acc[i][j] = fmaf(xv[i], wv[j], acc[i][j]);
        }
    }

    // fused attention terms: shuffle-reduce over the 4 lanes covering one head
    float ps[8], pd[8];
#pragma unroll
    for (int i = 0; i < 8; i++) {
        float s = 0.f, d = 0.f;
#pragma unroll
        for (int j = 0; j < 8; j++) {
            s = fmaf(acc[i][j], avs[j], s);
            d = fmaf(acc[i][j], avd[j], d);
        }
        ps[i] = s; pd[i] = d;
    }
#pragma unroll
    for (int off = 1; off < 4; off <<= 1) {
#pragma unroll
        for (int i = 0; i < 8; i++) {
            ps[i] += __shfl_xor_sync(0xffffffffu, ps[i], off);
            pd[i] += __shfl_xor_sync(0xffffffffu, pd[i], off);
        }
    }
    int head = tx >> 2;
    bool wr_att = ((tx & 3) == 0);

#pragma unroll
    for (int i = 0; i < 8; i++) {
        int gn = n0 + ty * 8 + i;
        if (gn < N_NODES) {
            __half2 h0 = __floats2half2_rn(acc[i][0], acc[i][1]);
            __half2 h1 = __floats2half2_rn(acc[i][2], acc[i][3]);
            __half2 h2 = __floats2half2_rn(acc[i][4], acc[i][5]);
            __half2 h3 = __floats2half2_rn(acc[i][6], acc[i][7]);
            uint4 v;
            v.x = *(const unsigned*)&h0;
            v.y = *(const unsigned*)&h1;
            v.z = *(const unsigned*)&h2;
            v.w = *(const unsigned*)&h3;
            *(uint4*)&g_hh[gn * HD + tx * 8] = v;
            if (wr_att) {
                g_asrc[gn * HEADS + head] = ps[i];
                g_adst[gn * HEADS + head] = pd[i];
            }
        }
    }
}

// ---------------- single-kernel scan: redundant prefix, no cross-block state ----------------
__global__ __launch_bounds__(512) void k_scan() {
    __shared__ int sh[512];
    int b = blockIdx.x, t = threadIdx.x;
    int base = b * 512;

    // phase 1: pre = sum g_cnt[0..base)
    int s = 0;
    for (int i = t; i < base; i += 512) s += g_cnt[i];
    sh[t] = s;
    __syncthreads();
    for (int off = 256; off > 0; off >>= 1) {
        if (t < off) sh[t] += sh[t + off];
        __syncthreads();
    }
    int pre = sh[0];
    __syncthreads();

    // phase 2: inclusive scan of this block's 512 counts
    int idx = base + t;
    int c = (idx < N_NODES) ? g_cnt[idx] : 0;
    sh[t] = c;
    __syncthreads();
    for (int off = 1; off < 512; off <<= 1) {
        int u = (t >= off) ? sh[t - off] : 0;
        __syncthreads();
        sh[t] += u;
        __syncthreads();
    }
    if (idx < N_NODES) g_off[idx] = pre + sh[t] - c;
    if (b == 0 && t == 0) g_off[N_NODES] = N_EDGES;
}

// ---------------- edge pass: logits -> exp (fp16) + CSR scatter + g_cnt reset ----------------
__global__ __launch_bounds__(256) void k_edge(const int* __restrict__ ei,
                                              const float* __restrict__ ea,
                                              const float* __restrict__ Wedge) {
    __shared__ float we[HEADS * EDGE_DIM];
    if (threadIdx.x < HEADS * EDGE_DIM) we[threadIdx.x] = Wedge[threadIdx.x];
    __syncthreads();

    int e = blockIdx.x * blockDim.x + threadIdx.x;
    // reset g_cnt for the NEXT launch (scan already consumed it this launch)
    if (e < N_NODES) g_cnt[e] = 0;
    if (e >= N_EDGES) return;

    int src = ei[e];
    int dst = ei[N_EDGES + e];

    const float4* ep = (const float4*)&ea[e * EDGE_DIM];
    float4 e0 = ep[0], e1 = ep[1], e2 = ep[2], e3 = ep[3];
    float ev[16] = {e0.x, e0.y, e0.z, e0.w, e1.x, e1.y, e1.z, e1.w,
                    e2.x, e2.y, e2.z, e2.w, e3.x, e3.y, e3.z, e3.w};

    float lg[4];
#pragma unroll
    for (int h = 0; h < 4; h++) {
        float s = 0.f;
#pragma unroll
        for (int k = 0; k < 16; k++) s = fmaf(ev[k], we[h * 16 + k], s);
        lg[h] = s;
    }

    float4 a4 = *(const float4*)&g_asrc[src * 4];
    float4 b4 = *(const float4*)&g_adst[dst * 4];
    lg[0] += a4.x + b4.x;
    lg[1] += a4.y + b4.y;
    lg[2] += a4.z + b4.z;
    lg[3] += a4.w + b4.w;
#pragma unroll
    for (int h = 0; h < 4; h++) {
        float v = (lg[h] > 0.f) ? lg[h] : 0.2f * lg[h];
        lg[h] = __expf(v);
    }

    int pos = g_off[dst] + g_rank[e];
    g_csr_src[pos] = src;
    __half2 x01 = __floats2half2_rn(lg[0], lg[1]);
    __half2 x23 = __floats2half2_rn(lg[2], lg[3]);
    uint2 pk;
    pk.x = *(const unsigned*)&x01;
    pk.y = *(const unsigned*)&x23;
    g_csr_exp[pos] = pk;
}

// ---------------- aggregation: warp per node, MLP-unrolled fp16 gather ----------------
__global__ __launch_bounds__(256) void k_agg(const float* __restrict__ bias,
                                             float* __restrict__ out) {
    __shared__ float s_alpha[8][32][4];
    __shared__ int   s_src[8][32];

    int warp = threadIdx.x >> 5;
    int lane = threadIdx.x & 31;
    int n = blockIdx.x * 8 + warp;
    if (n >= N_NODES) return;

    int beg = g_off[n];
    int end = g_off[n + 1];
    int myh = lane >> 3;

    // pass 1: denom per head
    float d0 = 0.f, d1 = 0.f, d2 = 0.f, d3 = 0.f;
    for (int i = beg + lane; i < end; i += 32) {
        uint2 r = g_csr_exp[i];
        float2 f01 = __half22float2(*(const __half2*)&r.x);
        float2 f23 = __half22float2(*(const __half2*)&r.y);
        d0 += f01.x; d1 += f01.y; d2 += f23.x; d3 += f23.y;
    }
#pragma unroll
    for (int off = 16; off > 0; off >>= 1) {
        d0 += __shfl_xor_sync(0xffffffffu, d0, off);
        d1 += __shfl_xor_sync(0xffffffffu, d1, off);
        d2 += __shfl_xor_sync(0xffffffffu, d2, off);
        d3 += __shfl_xor_sync(0xffffffffu, d3, off);
    }
    float i0 = 1.f / (d0 + 1e-16f);
    float i1 = 1.f / (d1 + 1e-16f);
    float i2 = 1.f / (d2 + 1e-16f);
    float i3 = 1.f / (d3 + 1e-16f);

    // pass 2: alpha-weighted gather of h[src], 4 loads in flight
    float4 acc = {0.f, 0.f, 0.f, 0.f};
    const __half* hh = g_hh;
    for (int c = beg; c < end; c += 32) {
        int i = c + lane;
        int nb = min(32, end - c);
        if (lane < nb) {
            uint2 r = g_csr_exp[i];
            float2 f01 = __half22float2(*(const __half2*)&r.x);
            float2 f23 = __half22float2(*(const __half2*)&r.y);
            s_src[warp][lane] = g_csr_src[i];
            s_alpha[warp][lane][0] = f01.x * i0;
            s_alpha[warp][lane][1] = f01.y * i1;
            s_alpha[warp][lane][2] = f23.x * i2;
            s_alpha[warp][lane][3] = f23.y * i3;
        }
        __syncwarp();
        int j = 0;
        for (; j + 4 <= nb; j += 4) {
            int sj0 = s_src[warp][j + 0];
            int sj1 = s_src[warp][j + 1];
            int sj2 = s_src[warp][j + 2];
            int sj3 = s_src[warp][j + 3];
            uint2 r0 = *(const uint2*)&hh[sj0 * HD + lane * 4];
            uint2 r1 = *(const uint2*)&hh[sj1 * HD + lane * 4];
            uint2 r2 = *(const uint2*)&hh[sj2 * HD + lane * 4];
            uint2 r3 = *(const uint2*)&hh[sj3 * HD + lane * 4];
            float a0 = s_alpha[warp][j + 0][myh];
            float a1 = s_alpha[warp][j + 1][myh];
            float a2 = s_alpha[warp][j + 2][myh];
            float a3 = s_alpha[warp][j + 3][myh];
            float2 f;
            f = __half22float2(*(const __half2*)&r0.x); acc.x = fmaf(a0, f.x, acc.x); acc.y = fmaf(a0, f.y, acc.y);
            f = __half22float2(*(const __half2*)&r0.y); acc.z = fmaf(a0, f.x, acc.z); acc.w = fmaf(a0, f.y, acc.w);
            f = __half22float2(*(const __half2*)&r1.x); acc.x = fmaf(a1, f.x, acc.x); acc.y = fmaf(a1, f.y, acc.y);
            f = __half22float2(*(const __half2*)&r1.y); acc.z = fmaf(a1, f.x, acc.z); acc.w = fmaf(a1, f.y, acc.w);
            f = __half22float2(*(const __half2*)&r2.x); acc.x = fmaf(a2, f.x, acc.x); acc.y = fmaf(a2, f.y, acc.y);
            f = __half22float2(*(const __half2*)&r2.y); acc.z = fmaf(a2, f.x, acc.z); acc.w = fmaf(a2, f.y, acc.w);
            f = __half22float2(*(const __half2*)&r3.x); acc.x = fmaf(a3, f.x, acc.x); acc.y = fmaf(a3, f.y, acc.y);
            f = __half22float2(*(const __half2*)&r3.y); acc.z = fmaf(a3, f.x, acc.z); acc.w = fmaf(a3, f.y, acc.w);
        }
        for (; j < nb; j++) {
            int sj = s_src[warp][j];
            float a = s_alpha[warp][j][myh];
            uint2 r = *(const uint2*)&hh[sj * HD + lane * 4];
            float2 f01 = __half22float2(*(const __half2*)&r.x);
            float2 f23 = __half22float2(*(const __half2*)&r.y);
            acc.x = fmaf(a, f01.x, acc.x);
            acc.y = fmaf(a, f01.y, acc.y);
            acc.z = fmaf(a, f23.x, acc.z);
            acc.w = fmaf(a, f23.y, acc.w);
        }
        __syncwarp();
    }

    // reduce over heads
    acc.x += __shfl_xor_sync(0xffffffffu, acc.x, 8);
    acc.y += __shfl_xor_sync(0xffffffffu, acc.y, 8);
    acc.z += __shfl_xor_sync(0xffffffffu, acc.z, 8);
    acc.w += __shfl_xor_sync(0xffffffffu, acc.w, 8);
    acc.x += __shfl_xor_sync(0xffffffffu, acc.x, 16);
    acc.y += __shfl_xor_sync(0xffffffffu, acc.y, 16);
    acc.z += __shfl_xor_sync(0xffffffffu, acc.z, 16);
    acc.w += __shfl_xor_sync(0xffffffffu, acc.w, 16);

    if (lane < 8) {
        float4 b4 = *(const float4*)&bias[lane * 4];
        float4 o;
        o.x = acc.x * 0.25f + b4.x;
        o.y = acc.y * 0.25f + b4.y;
        o.z = acc.z * 0.25f + b4.z;
        o.w = acc.w * 0.25f + b4.w;
        *(float4*)&out[n * OUT_DIM + lane * 4] = o;
    }
}

// ---------------- launch: 5 kernels; index 3 (k_edge) is the profiled one ----------------
extern "C" void kernel_launch(void* const* d_in, const int* in_sizes, int n_in,
                              void* d_out, int out_size) {
    const float* x    = (const float*)d_in[0];
    const int*   ei   = (const int*)  d_in[1];
    const float* ea   = (const float*)d_in[2];
    const float* Wl   = (const float*)d_in[3];
    const float* as   = (const float*)d_in[4];
    const float* ad   = (const float*)d_in[5];
    const float* bias = (const float*)d_in[6];
    const float* We   = (const float*)d_in[7];
    float* out = (float*)d_out;

    k_hist <<<(N_EDGES / 4 + 255) / 256, 256>>>(ei);
    k_gemm <<<(N_NODES + 127) / 128, 256>>>(x, Wl, as, ad);
    k_scan <<<98, 512>>>();
    k_edge <<<(N_EDGES + 255) / 256, 256>>>(ei, ea, We);
    k_agg  <<<(N_NODES + 7) / 8, 256>>>(bias, out);
}

// round 9
// speedup vs baseline: 1.1134x; 1.1134x over previous
#include <cuda_runtime.h>
#include <cuda_fp16.h>

#define N_NODES 50000
#define N_EDGES 1600000
#define IN_DIM 128
#define OUT_DIM 32
#define HEADS 4
#define HD 128           // HEADS * OUT_DIM
#define EDGE_DIM 16

// ---------------- device scratch (static: no allocation allowed) ----------------
// g_cnt invariant: all-zero at kernel_launch entry. First call: .bss zero-init.
// Every call: k_edge re-zeroes it (after k_scan consumed it, before next call's k_hist).
__device__ __half g_hh[N_NODES * HD];         // 12.8 MB  h (fp16)
__device__ float g_WT[IN_DIM * HD];           // 64 KB    W transposed [k][j]
__device__ float g_asrc[N_NODES * HEADS];
__device__ float g_adst[N_NODES * HEADS];
__device__ int   g_cnt[N_NODES];
__device__ int   g_off[N_NODES + 1];
__device__ int   g_rank[N_EDGES];             // rank of edge within its dst segment
__device__ uint4 g_csr[N_EDGES];              // 25.6 MB: {src, exp01(h2), exp23(h2), pad}

// ---------------- hist: 4 edges/thread for MLP ----------------
__global__ void k_hist(const int* __restrict__ ei) {
    int i = blockIdx.x * blockDim.x + threadIdx.x;
    if (i < N_EDGES / 4) {
        int4 d4 = ((const int4*)(ei + N_EDGES))[i];
        int4 r;
        r.x = atomicAdd(&g_cnt[d4.x], 1);
        r.y = atomicAdd(&g_cnt[d4.y], 1);
        r.z = atomicAdd(&g_cnt[d4.z], 1);
        r.w = atomicAdd(&g_cnt[d4.w], 1);
        ((int4*)g_rank)[i] = r;
    }
}

// ---------------- W [j][k] row-major -> WT [k][j] ----------------
__global__ void k_transW(const float* __restrict__ W) {
    int j = blockIdx.x;
    int k = threadIdx.x;
    g_WT[k * HD + j] = W[j * IN_DIM + k];
}

// ---------------- single-kernel scan: redundant prefix, no cross-block state ----------------
__global__ __launch_bounds__(512) void k_scan() {
    __shared__ int sh[512];
    int b = blockIdx.x, t = threadIdx.x;
    int base = b * 512;

    // phase 1: pre = sum g_cnt[0..base)
    int s = 0;
    for (int i = t; i < base; i += 512) s += g_cnt[i];
    sh[t] = s;
    __syncthreads();
    for (int off = 256; off > 0; off >>= 1) {
        if (t < off) sh[t] += sh[t + off];
        __syncthreads();
    }
    int pre = sh[0];
    __syncthreads();

    // phase 2: inclusive scan of this block's 512 counts
    int idx = base + t;
    int c = (idx < N_NODES) ? g_cnt[idx] : 0;
    sh[t] = c;
    __syncthreads();
    for (int off = 1; off < 512; off <<= 1) {
        int u = (t >= off) ? sh[t - off] : 0;
        __syncthreads();
        sh[t] += u;
        __syncthreads();
    }
    if (idx < N_NODES) g_off[idx] = pre + sh[t] - c;
    if (b == 0 && t == 0) g_off[N_NODES] = N_EDGES;
}

// ---------------- GEMM: h = x@W^T, 128x128 tile, 256 thr, 8x8/thread ----------------
__global__ __launch_bounds__(256) void k_gemm(const float* __restrict__ x,
                                              const float* __restrict__ att_src,
                                              const float* __restrict__ att_dst) {
    __shared__ float ws[32][136];   // W chunk [kk][j], padded
    __shared__ float xs[128][33];   // x chunk [n][kk], padded

    int tid = threadIdx.x;
    int tx = tid & 15;      // cols tx*8 .. tx*8+7
    int ty = tid >> 4;      // nodes ty*8 .. ty*8+7
    int n0 = blockIdx.x * 128;

    float avs[8], avd[8];
    {
        float4 s0 = __ldg((const float4*)&att_src[tx * 8]);
        float4 s1 = __ldg((const float4*)&att_src[tx * 8 + 4]);
        float4 d0 = __ldg((const float4*)&att_dst[tx * 8]);
        float4 d1 = __ldg((const float4*)&att_dst[tx * 8 + 4]);
        avs[0]=s0.x; avs[1]=s0.y; avs[2]=s0.z; avs[3]=s0.w;
        avs[4]=s1.x; avs[5]=s1.y; avs[6]=s1.z; avs[7]=s1.w;
        avd[0]=d0.x; avd[1]=d0.y; avd[2]=d0.z; avd[3]=d0.w;
        avd[4]=d1.x; avd[5]=d1.y; avd[6]=d1.z; avd[7]=d1.w;
    }

    float acc[8][8];
#pragma unroll
    for (int i = 0; i < 8; i++)
#pragma unroll
        for (int j = 0; j < 8; j++) acc[i][j] = 0.f;

    for (int kc = 0; kc < IN_DIM; kc += 32) {
        __syncthreads();
        // W chunk from pre-transposed g_WT: fully coalesced
        for (int i = tid; i < 32 * HD; i += 256) {
            int kk = i >> 7, j = i & 127;
            ws[kk][j] = g_WT[(kc + kk) * HD + j];
        }
        // x chunk: 128 nodes x 32 k, coalesced
        for (int i = tid; i < 128 * 32; i += 256) {
            int nn = i >> 5, kk = i & 31;
            int gn = n0 + nn;
            xs[nn][kk] = (gn < N_NODES) ? x[gn * IN_DIM + kc + kk] : 0.f;
        }
        __syncthreads();

#pragma unroll 4
        for (int kk = 0; kk < 32; kk++) {
            float4 w0 = *(const float4*)&ws[kk][tx * 8];
            float4 w1 = *(const float4*)&ws[kk][tx * 8 + 4];
            float wv[8] = {w0.x, w0.y, w0.z, w0.w, w1.x, w1.y, w1.z, w1.w};
            float xv[8];
#pragma unroll
            for (int i = 0; i < 8; i++) xv[i] = xs[ty * 8 + i][kk];
#pragma unroll
            for (int i = 0; i < 8; i++)
#pragma unroll
                for (int j = 0; j < 8; j++)
                    acc[i][j] = fmaf(xv[i], wv[j], acc[i][j]);
        }
    }

    // fused attention terms: shuffle-reduce over the 4 lanes covering one head
    float ps[8], pd[8];
#pragma unroll
    for (int i = 0; i < 8; i++) {
        float s = 0.f, d = 0.f;
#pragma unroll
        for (int j = 0; j < 8; j++) {
            s = fmaf(acc[i][j], avs[j], s);
            d = fmaf(acc[i][j], avd[j], d);
        }
        ps[i] = s; pd[i] = d;
    }
#pragma unroll
    for (int off = 1; off < 4; off <<= 1) {
#pragma unroll
        for (int i = 0; i < 8; i++) {
            ps[i] += __shfl_xor_sync(0xffffffffu, ps[i], off);
            pd[i] += __shfl_xor_sync(0xffffffffu, pd[i], off);
        }
    }
    int head = tx >> 2;
    bool wr_att = ((tx & 3) == 0);

#pragma unroll
    for (int i = 0; i < 8; i++) {
        int gn = n0 + ty * 8 + i;
        if (gn < N_NODES) {
            __half2 h0 = __floats2half2_rn(acc[i][0], acc[i][1]);
            __half2 h1 = __floats2half2_rn(acc[i][2], acc[i][3]);
            __half2 h2 = __floats2half2_rn(acc[i][4], acc[i][5]);
            __half2 h3 = __floats2half2_rn(acc[i][6], acc[i][7]);
            uint4 v;
            v.x = *(const unsigned*)&h0;
            v.y = *(const unsigned*)&h1;
            v.z = *(const unsigned*)&h2;
            v.w = *(const unsigned*)&h3;
            *(uint4*)&g_hh[gn * HD + tx * 8] = v;
            if (wr_att) {
                g_asrc[gn * HEADS + head] = ps[i];
                g_adst[gn * HEADS + head] = pd[i];
            }
        }
    }
}

// ---------------- edge pass: 2 edges/thread, single 16B CSR record scatter ----------------
__global__ __launch_bounds__(256) void k_edge(const int* __restrict__ ei,
                                              const float* __restrict__ ea,
                                              const float* __restrict__ Wedge) {
    __shared__ float we[HEADS * EDGE_DIM];
    if (threadIdx.x < HEADS * EDGE_DIM) we[threadIdx.x] = Wedge[threadIdx.x];
    __syncthreads();

    int gidx = blockIdx.x * blockDim.x + threadIdx.x;
    // reset g_cnt for the NEXT launch (scan already consumed it this launch)
    if (gidx < N_NODES) g_cnt[gidx] = 0;

    int e0 = blockIdx.x * (blockDim.x * 2) + threadIdx.x;
#pragma unroll
    for (int u = 0; u < 2; u++) {
        int e = e0 + u * 256;
        if (e >= N_EDGES) break;

        int src = ei[e];
        int dst = ei[N_EDGES + e];

        const float4* ep = (const float4*)&ea[e * EDGE_DIM];
        float4 q0 = ep[0], q1 = ep[1], q2 = ep[2], q3 = ep[3];
        float4 a4 = *(const float4*)&g_asrc[src * 4];
        float4 b4 = *(const float4*)&g_adst[dst * 4];
        float ev[16] = {q0.x, q0.y, q0.z, q0.w, q1.x, q1.y, q1.z, q1.w,
                        q2.x, q2.y, q2.z, q2.w, q3.x, q3.y, q3.z, q3.w};

        float lg[4];
#pragma unroll
        for (int h = 0; h < 4; h++) {
            float s = 0.f;
#pragma unroll
            for (int k = 0; k < 16; k++) s = fmaf(ev[k], we[h * 16 + k], s);
            lg[h] = s;
        }
        lg[0] += a4.x + b4.x;
        lg[1] += a4.y + b4.y;
        lg[2] += a4.z + b4.z;
        lg[3] += a4.w + b4.w;
#pragma unroll
        for (int h = 0; h < 4; h++) {
            float v = (lg[h] > 0.f) ? lg[h] : 0.2f * lg[h];
            lg[h] = __expf(v);
        }

        int pos = g_off[dst] + g_rank[e];
        __half2 x01 = __floats2half2_rn(lg[0], lg[1]);
        __half2 x23 = __floats2half2_rn(lg[2], lg[3]);
        uint4 rec;
        rec.x = (unsigned)src;
        rec.y = *(const unsigned*)&x01;
        rec.z = *(const unsigned*)&x23;
        rec.w = 0u;
        g_csr[pos] = rec;
    }
}

// ---------------- aggregation: warp per node, MLP-unrolled fp16 gather ----------------
__global__ __launch_bounds__(256) void k_agg(const float* __restrict__ bias,
                                             float* __restrict__ out) {
    __shared__ float s_alpha[8][32][4];
    __shared__ int   s_src[8][32];

    int warp = threadIdx.x >> 5;
    int lane = threadIdx.x & 31;
    int n = blockIdx.x * 8 + warp;
    if (n >= N_NODES) return;

    int beg = g_off[n];
    int end = g_off[n + 1];
    int myh = lane >> 3;

    // pass 1: denom per head
    float d0 = 0.f, d1 = 0.f, d2 = 0.f, d3 = 0.f;
    for (int i = beg + lane; i < end; i += 32) {
        uint4 r = g_csr[i];
        float2 f01 = __half22float2(*(const __half2*)&r.y);
        float2 f23 = __half22float2(*(const __half2*)&r.z);
        d0 += f01.x; d1 += f01.y; d2 += f23.x; d3 += f23.y;
    }
#pragma unroll
    for (int off = 16; off > 0; off >>= 1) {
        d0 += __shfl_xor_sync(0xffffffffu, d0, off);
        d1 += __shfl_xor_sync(0xffffffffu, d1, off);
        d2 += __shfl_xor_sync(0xffffffffu, d2, off);
        d3 += __shfl_xor_sync(0xffffffffu, d3, off);
    }
    float i0 = 1.f / (d0 + 1e-16f);
    float i1 = 1.f / (d1 + 1e-16f);
    float i2 = 1.f / (d2 + 1e-16f);
    float i3 = 1.f / (d3 + 1e-16f);

    // pass 2: alpha-weighted gather of h[src], 4 loads in flight
    float4 acc = {0.f, 0.f, 0.f, 0.f};
    const __half* hh = g_hh;
    for (int c = beg; c < end; c += 32) {
        int i = c + lane;
        int nb = min(32, end - c);
        if (lane < nb) {
            uint4 r = g_csr[i];
            float2 f01 = __half22float2(*(const __half2*)&r.y);
            float2 f23 = __half22float2(*(const __half2*)&r.z);
            s_src[warp][lane] = (int)r.x;
            s_alpha[warp][lane][0] = f01.x * i0;
            s_alpha[warp][lane][1] = f01.y * i1;
            s_alpha[warp][lane][2] = f23.x * i2;
            s_alpha[warp][lane][3] = f23.y * i3;
        }
        __syncwarp();
        int j = 0;
        for (; j + 4 <= nb; j += 4) {
            int sj0 = s_src[warp][j + 0];
            int sj1 = s_src[warp][j + 1];
            int sj2 = s_src[warp][j + 2];
            int sj3 = s_src[warp][j + 3];
            uint2 r0 = *(const uint2*)&hh[sj0 * HD + lane * 4];
            uint2 r1 = *(const uint2*)&hh[sj1 * HD + lane * 4];
            uint2 r2 = *(const uint2*)&hh[sj2 * HD + lane * 4];
            uint2 r3 = *(const uint2*)&hh[sj3 * HD + lane * 4];
            float a0 = s_alpha[warp][j + 0][myh];
            float a1 = s_alpha[warp][j + 1][myh];
            float a2 = s_alpha[warp][j + 2][myh];
            float a3 = s_alpha[warp][j + 3][myh];
            float2 f;
            f = __half22float2(*(const __half2*)&r0.x); acc.x = fmaf(a0, f.x, acc.x); acc.y = fmaf(a0, f.y, acc.y);
            f = __half22float2(*(const __half2*)&r0.y); acc.z = fmaf(a0, f.x, acc.z); acc.w = fmaf(a0, f.y, acc.w);
            f = __half22float2(*(const __half2*)&r1.x); acc.x = fmaf(a1, f.x, acc.x); acc.y = fmaf(a1, f.y, acc.y);
            f = __half22float2(*(const __half2*)&r1.y); acc.z = fmaf(a1, f.x, acc.z); acc.w = fmaf(a1, f.y, acc.w);
            f = __half22float2(*(const __half2*)&r2.x); acc.x = fmaf(a2, f.x, acc.x); acc.y = fmaf(a2, f.y, acc.y);
            f = __half22float2(*(const __half2*)&r2.y); acc.z = fmaf(a2, f.x, acc.z); acc.w = fmaf(a2, f.y, acc.w);
            f = __half22float2(*(const __half2*)&r3.x); acc.x = fmaf(a3, f.x, acc.x); acc.y = fmaf(a3, f.y, acc.y);
            f = __half22float2(*(const __half2*)&r3.y); acc.z = fmaf(a3, f.x, acc.z); acc.w = fmaf(a3, f.y, acc.w);
        }
        for (; j < nb; j++) {
            int sj = s_src[warp][j];
            float a = s_alpha[warp][j][myh];
            uint2 r = *(const uint2*)&hh[sj * HD + lane * 4];
            float2 f01 = __half22float2(*(const __half2*)&r.x);
            float2 f23 = __half22float2(*(const __half2*)&r.y);
            acc.x = fmaf(a, f01.x, acc.x);
            acc.y = fmaf(a, f01.y, acc.y);
            acc.z = fmaf(a, f23.x, acc.z);
            acc.w = fmaf(a, f23.y, acc.w);
        }
        __syncwarp();
    }

    // reduce over heads
    acc.x += __shfl_xor_sync(0xffffffffu, acc.x, 8);
    acc.y += __shfl_xor_sync(0xffffffffu, acc.y, 8);
    acc.z += __shfl_xor_sync(0xffffffffu, acc.z, 8);
    acc.w += __shfl_xor_sync(0xffffffffu, acc.w, 8);
    acc.x += __shfl_xor_sync(0xffffffffu, acc.x, 16);
    acc.y += __shfl_xor_sync(0xffffffffu, acc.y, 16);
    acc.z += __shfl_xor_sync(0xffffffffu, acc.z, 16);
    acc.w += __shfl_xor_sync(0xffffffffu, acc.w, 16);

    if (lane < 8) {
        float4 b4 = *(const float4*)&bias[lane * 4];
        float4 o;
        o.x = acc.x * 0.25f + b4.x;
        o.y = acc.y * 0.25f + b4.y;
        o.z = acc.z * 0.25f + b4.z;
        o.w = acc.w * 0.25f + b4.w;
        *(float4*)&out[n * OUT_DIM + lane * 4] = o;
    }
}

// ---------------- launch: 6 kernels; index 3 (k_gemm) is the profiled one ----------------
extern "C" void kernel_launch(void* const* d_in, const int* in_sizes, int n_in,
                              void* d_out, int out_size) {
    const float* x    = (const float*)d_in[0];
    const int*   ei   = (const int*)  d_in[1];
    const float* ea   = (const float*)d_in[2];
    const float* Wl   = (const float*)d_in[3];
    const float* as   = (const float*)d_in[4];
    const float* ad   = (const float*)d_in[5];
    const float* bias = (const float*)d_in[6];
    const float* We   = (const float*)d_in[7];
    float* out = (float*)d_out;

    k_hist  <<<(N_EDGES / 4 + 255) / 256, 256>>>(ei);
    k_transW<<<IN_DIM, HD>>>(Wl);
    k_scan  <<<98, 512>>>();
    k_gemm  <<<(N_NODES + 127) / 128, 256>>>(x, as, ad);
    k_edge  <<<(N_EDGES + 511) / 512, 256>>>(ei, ea, We);
    k_agg   <<<(N_NODES + 7) / 8, 256>>>(bias, out);
}

// round 11
// speedup vs baseline: 1.6391x; 1.4722x over previous
#include <cuda_runtime.h>
#include <cuda_fp16.h>

#define N_NODES 50000
#define N_EDGES 1600000
#define IN_DIM 128
#define OUT_DIM 32
#define HEADS 4
#define HD 128           // HEADS * OUT_DIM
#define EDGE_DIM 16

// ---------------- device scratch (static: no allocation allowed) ----------------
// g_cnt invariant: all-zero at kernel_launch entry. First call: .bss zero-init.
// Every call: k_edge re-zeroes it (after k_scan consumed it, before next call's k_hist).
__device__ __half g_hh[N_NODES * HD];         // 12.8 MB  h (fp16)
__device__ unsigned g_Wfrag[8 * 16 * 32 * 2]; // 16 KB: B fragments [kstep][ntile][lane][2]
__device__ float g_asrc[N_NODES * HEADS];
__device__ float g_adst[N_NODES * HEADS];
__device__ int   g_cnt[N_NODES];
__device__ int   g_off[N_NODES + 1];
__device__ int   g_rank[N_EDGES];             // rank of edge within its dst segment
__device__ uint4 g_csr[N_EDGES];              // 25.6 MB: {src, exp01(h2), exp23(h2), pad}

// ---------------- hist: 4 edges/thread for MLP ----------------
__global__ void k_hist(const int* __restrict__ ei) {
    int i = blockIdx.x * blockDim.x + threadIdx.x;
    if (i < N_EDGES / 4) {
        int4 d4 = ((const int4*)(ei + N_EDGES))[i];
        int4 r;
        r.x = atomicAdd(&g_cnt[d4.x], 1);
        r.y = atomicAdd(&g_cnt[d4.y], 1);
        r.z = atomicAdd(&g_cnt[d4.z], 1);
        r.w = atomicAdd(&g_cnt[d4.w], 1);
        ((int4*)g_rank)[i] = r;
    }
}

// ---------------- W -> per-lane fp16 B fragments for mma.m16n8k16.row.col ----------------
// Lane l (q=l&3, g=l>>2) of tile (kstep s, ntile t): b0 = W[t*8+g][s*16+2q..+1],
// b1 = W[t*8+g][s*16+2q+8..+9]  (B is col-major KxN with n=g, k=2q..).
__global__ void k_transW(const float* __restrict__ W) {
    int i = blockIdx.x * blockDim.x + threadIdx.x;   // 0..4095
    int l = i & 31;
    int t = (i >> 5) & 15;
    int s = i >> 9;
    int q = l & 3, g = l >> 2;
    int j = t * 8 + g;               // output column
    int k0 = s * 16 + 2 * q;         // k index
    float w00 = W[j * IN_DIM + k0];
    float w01 = W[j * IN_DIM + k0 + 1];
    float w10 = W[j * IN_DIM + k0 + 8];
    float w11 = W[j * IN_DIM + k0 + 9];
    __half2 b0 = __floats2half2_rn(w00, w01);
    __half2 b1 = __floats2half2_rn(w10, w11);
    uint2 o;
    o.x = *(unsigned*)&b0;
    o.y = *(unsigned*)&b1;
    ((uint2*)g_Wfrag)[i] = o;
}

// ---------------- single-kernel scan: redundant prefix, no cross-block state ----------------
__global__ __launch_bounds__(512) void k_scan() {
    __shared__ int sh[512];
    int b = blockIdx.x, t = threadIdx.x;
    int base = b * 512;

    int s = 0;
    for (int i = t; i < base; i += 512) s += g_cnt[i];
    sh[t] = s;
    __syncthreads();
    for (int off = 256; off > 0; off >>= 1) {
        if (t < off) sh[t] += sh[t + off];
        __syncthreads();
    }
    int pre = sh[0];
    __syncthreads();

    int idx = base + t;
    int c = (idx < N_NODES) ? g_cnt[idx] : 0;
    sh[t] = c;
    __syncthreads();
    for (int off = 1; off < 512; off <<= 1) {
        int u = (t >= off) ? sh[t - off] : 0;
        __syncthreads();
        sh[t] += u;
        __syncthreads();
    }
    if (idx < N_NODES) g_off[idx] = pre + sh[t] - c;
    if (b == 0 && t == 0) g_off[N_NODES] = N_EDGES;
}

// ---------------- GEMM: h = x@W^T via mma.sync m16n8k16 (fp16 in, fp32 acc) ----------------
// Block: 128 nodes x 128 cols, 8 warps = 4(M) x 2(N); warp tile 32x64.
__global__ __launch_bounds__(256) void k_gemm(const float* __restrict__ x,
                                              const float* __restrict__ att_src,
                                              const float* __restrict__ att_dst) {
    __shared__ __align__(16) __half sh[128 * 136];   // x tile, later h staging (34816 B)

    int tid = threadIdx.x;
    int n0 = blockIdx.x * 128;
    int warp = tid >> 5, lane = tid & 31;
    int wm = warp & 3;     // 0-3: rows wm*32..+31
    int wn = warp >> 2;    // 0-1: cols wn*64..+63
    int q = lane & 3, g = lane >> 2;

    // ---- load + convert x tile (fp32 -> fp16 smem): 128 rows x 32 float4s = 4096 ----
#pragma unroll
    for (int r = 0; r < 16; r++) {
        int uidx = r * 256 + tid;          // 0..4095
        int row = uidx >> 5, c4 = uidx & 31;
        int gn = n0 + row;
        float4 v = {0.f, 0.f, 0.f, 0.f};
        if (gn < N_NODES) v = *(const float4*)&x[gn * IN_DIM + c4 * 4];
        __half2 p0 = __floats2half2_rn(v.x, v.y);
        __half2 p1 = __floats2half2_rn(v.z, v.w);
        uint2 pk;
        pk.x = *(unsigned*)&p0;
        pk.y = *(unsigned*)&p1;
        *(uint2*)&sh[row * 136 + c4 * 4] = pk;
    }
    __syncthreads();

    float acc[2][8][4];
#pragma unroll
    for (int m = 0; m < 2; m++)
#pragma unroll
        for (int nt = 0; nt < 8; nt++)
#pragma unroll
            for (int c = 0; c < 4; c++) acc[m][nt][c] = 0.f;

    const uint2* wf = (const uint2*)g_Wfrag;
    for (int s = 0; s < 8; s++) {
        // A fragments: lane l holds rows (g, g+8), cols (2q,2q+1) and (+8)
        unsigned a[2][4];
#pragma unroll
        for (int m = 0; m < 2; m++) {
            int r0 = wm * 32 + m * 16 + g;
            int c0 = s * 16 + 2 * q;
            a[m][0] = *(const unsigned*)&sh[r0 * 136 + c0];
            a[m][1] = *(const unsigned*)&sh[(r0 + 8) * 136 + c0];
            a[m][2] = *(const unsigned*)&sh[r0 * 136 + c0 + 8];
            a[m][3] = *(const unsigned*)&sh[(r0 + 8) * 136 + c0 + 8];
        }
#pragma unroll
        for (int nt = 0; nt < 8; nt++) {
            uint2 b = wf[(s * 16 + wn * 8 + nt) * 32 + lane];
#pragma unroll
            for (int m = 0; m < 2; m++) {
                asm volatile(
                    "mma.sync.aligned.m16n8k16.row.col.f32.f16.f16.f32 "
                    "{%0,%1,%2,%3}, {%4,%5,%6,%7}, {%8,%9}, {%0,%1,%2,%3};"
                    : "+f"(acc[m][nt][0]), "+f"(acc[m][nt][1]),
                      "+f"(acc[m][nt][2]), "+f"(acc[m][nt][3])
                    : "r"(a[m][0]), "r"(a[m][1]), "r"(a[m][2]), "r"(a[m][3]),
                      "r"(b.x), "r"(b.y));
            }
        }
    }

    // ---- fused a_src/a_dst from fp32 fragments ----
    // lane's cols: j = wn*64 + nt*8 + 2q + {0,1}; head = wn*2 + (nt>>2)
    float2 as2[8], ad2[8];
#pragma unroll
    for (int nt = 0; nt < 8; nt++) {
        int j = wn * 64 + nt * 8 + 2 * q;
        as2[nt] = *(const float2*)&att_src[j];
        ad2[nt] = *(const float2*)&att_dst[j];
    }
#pragma unroll
    for (int m = 0; m < 2; m++) {
        float v[8] = {0.f, 0.f, 0.f, 0.f, 0.f, 0.f, 0.f, 0.f};
        // v: [r0_h0_s, r0_h1_s, r0_h0_d, r0_h1_d, r1_h0_s, r1_h1_s, r1_h0_d, r1_h1_d]
#pragma unroll
        for (int nt = 0; nt < 8; nt++) {
            int hsel = (nt >> 2);   // 0 or 1
            float ax0 = acc[m][nt][0], ax1 = acc[m][nt][1];
            float ay0 = acc[m][nt][2], ay1 = acc[m][nt][3];
            v[0 + hsel] += ax0 * as2[nt].x + ax1 * as2[nt].y;
            v[2 + hsel] += ax0 * ad2[nt].x + ax1 * ad2[nt].y;
            v[4 + hsel] += ay0 * as2[nt].x + ay1 * as2[nt].y;
            v[6 + hsel] += ay0 * ad2[nt].x + ay1 * ad2[nt].y;
        }
#pragma unroll
        for (int k = 0; k < 8; k++) {
            v[k] += __shfl_xor_sync(0xffffffffu, v[k], 1);
            v[k] += __shfl_xor_sync(0xffffffffu, v[k], 2);
        }
        if (q == 0) {
            int node0 = n0 + wm * 32 + m * 16 + g;
            int node1 = node0 + 8;
            if (node0 < N_NODES) {
                g_asrc[node0 * 4 + wn * 2 + 0] = v[0];
                g_asrc[node0 * 4 + wn * 2 + 1] = v[1];
                g_adst[node0 * 4 + wn * 2 + 0] = v[2];
                g_adst[node0 * 4 + wn * 2 + 1] = v[3];
            }
            if (node1 < N_NODES) {
                g_asrc[node1 * 4 + wn * 2 + 0] = v[4];
                g_asrc[node1 * 4 + wn * 2 + 1] = v[5];
                g_adst[node1 * 4 + wn * 2 + 0] = v[6];
                g_adst[node1 * 4 + wn * 2 + 1] = v[7];
            }
        }
    }

    // ---- stage h (fp16) into smem, then coalesced global write ----
    __syncthreads();   // all warps done reading x from sh
#pragma unroll
    for (int m = 0; m < 2; m++) {
        int r0 = wm * 32 + m * 16 + g;
#pragma unroll
        for (int nt = 0; nt < 8; nt++) {
            int col = wn * 64 + nt * 8 + 2 * q;
            __half2 h0 = __floats2half2_rn(acc[m][nt][0], acc[m][nt][1]);
            __half2 h1 = __floats2half2_rn(acc[m][nt][2], acc[m][nt][3]);
            *(unsigned*)&sh[r0 * 136 + col] = *(unsigned*)&h0;
            *(unsigned*)&sh[(r0 + 8) * 136 + col] = *(unsigned*)&h1;
        }
    }
    __syncthreads();
#pragma unroll
    for (int r = 0; r < 8; r++) {
        int uidx = r * 256 + tid;          // 2048 uint4s = 128 rows x 16
        int row = uidx >> 4, c16 = uidx & 15;
        int gn = n0 + row;
        if (gn < N_NODES) {
            uint4 vv = *(const uint4*)&sh[row * 136 + c16 * 8];
            *(uint4*)&g_hh[gn * HD + c16 * 8] = vv;
        }
    }
}

// ---------------- edge pass: 2 edges/thread, single 16B CSR record scatter ----------------
__global__ __launch_bounds__(256) void k_edge(const int* __restrict__ ei,
                                              const float* __restrict__ ea,
                                              const float* __restrict__ Wedge) {
    __shared__ float we[HEADS * EDGE_DIM];
    if (threadIdx.x < HEADS * EDGE_DIM) we[threadIdx.x] = Wedge[threadIdx.x];
    __syncthreads();

    int gidx = blockIdx.x * blockDim.x + threadIdx.x;
    // reset g_cnt for the NEXT launch (scan already consumed it this launch)
    if (gidx < N_NODES) g_cnt[gidx] = 0;

    int e0 = blockIdx.x * (blockDim.x * 2) + threadIdx.x;
#pragma unroll
    for (int u = 0; u < 2; u++) {
        int e = e0 + u * 256;
        if (e >= N_EDGES) break;

        int src = ei[e];
        int dst = ei[N_EDGES + e];

        const float4* ep = (const float4*)&ea[e * EDGE_DIM];
        float4 q0 = ep[0], q1 = ep[1], q2 = ep[2], q3 = ep[3];
        float4 a4 = *(const float4*)&g_asrc[src * 4];
        float4 b4 = *(const float4*)&g_adst[dst * 4];
        float ev[16] = {q0.x, q0.y, q0.z, q0.w, q1.x, q1.y, q1.z, q1.w,
                        q2.x, q2.y, q2.z, q2.w, q3.x, q3.y, q3.z, q3.w};

        float lg[4];
#pragma unroll
        for (int h = 0; h < 4; h++) {
            float s = 0.f;
#pragma unroll
            for (int k = 0; k < 16; k++) s = fmaf(ev[k], we[h * 16 + k], s);
            lg[h] = s;
        }
        lg[0] += a4.x + b4.x;
        lg[1] += a4.y + b4.y;
        lg[2] += a4.z + b4.z;
        lg[3] += a4.w + b4.w;
#pragma unroll
        for (int h = 0; h < 4; h++) {
            float v = (lg[h] > 0.f) ? lg[h] : 0.2f * lg[h];
            lg[h] = __expf(v);
        }

        int pos = g_off[dst] + g_rank[e];
        __half2 x01 = __floats2half2_rn(lg[0], lg[1]);
        __half2 x23 = __floats2half2_rn(lg[2], lg[3]);
        uint4 rec;
        rec.x = (unsigned)src;
        rec.y = *(const unsigned*)&x01;
        rec.z = *(const unsigned*)&x23;
        rec.w = 0u;
        g_csr[pos] = rec;
    }
}

// ---------------- aggregation: warp per node, MLP-unrolled fp16 gather ----------------
__global__ __launch_bounds__(256) void k_agg(const float* __restrict__ bias,
                                             float* __restrict__ out) {
    __shared__ float s_alpha[8][32][4];
    __shared__ int   s_src[8][32];

    int warp = threadIdx.x >> 5;
    int lane = threadIdx.x & 31;
    int n = blockIdx.x * 8 + warp;
    if (n >= N_NODES) return;

    int beg = g_off[n];
    int end = g_off[n + 1];
    int myh = lane >> 3;

    // pass 1: denom per head
    float d0 = 0.f, d1 = 0.f, d2 = 0.f, d3 = 0.f;
    for (int i = beg + lane; i < end; i += 32) {
        uint4 r = g_csr[i];
        float2 f01 = __half22float2(*(const __half2*)&r.y);
        float2 f23 = __half22float2(*(const __half2*)&r.z);
        d0 += f01.x; d1 += f01.y; d2 += f23.x; d3 += f23.y;
    }
#pragma unroll
    for (int off = 16; off > 0; off >>= 1) {
        d0 += __shfl_xor_sync(0xffffffffu, d0, off);
        d1 += __shfl_xor_sync(0xffffffffu, d1, off);
        d2 += __shfl_xor_sync(0xffffffffu, d2, off);
        d3 += __shfl_xor_sync(0xffffffffu, d3, off);
    }
    float i0 = 1.f / (d0 + 1e-16f);
    float i1 = 1.f / (d1 + 1e-16f);
    float i2 = 1.f / (d2 + 1e-16f);
    float i3 = 1.f / (d3 + 1e-16f);

    // pass 2: alpha-weighted gather of h[src], 4 loads in flight
    float4 acc = {0.f, 0.f, 0.f, 0.f};
    const __half* hh = g_hh;
    for (int c = beg; c < end; c += 32) {
        int i = c + lane;
        int nb = min(32, end - c);
        if (lane < nb) {
            uint4 r = g_csr[i];
            float2 f01 = __half22float2(*(const __half2*)&r.y);
            float2 f23 = __half22float2(*(const __half2*)&r.z);
            s_src[warp][lane] = (int)r.x;
            s_alpha[warp][lane][0] = f01.x * i0;
            s_alpha[warp][lane][1] = f01.y * i1;
            s_alpha[warp][lane][2] = f23.x * i2;
            s_alpha[warp][lane][3] = f23.y * i3;
        }
        __syncwarp();
        int j = 0;
        for (; j + 4 <= nb; j += 4) {
            int sj0 = s_src[warp][j + 0];
            int sj1 = s_src[warp][j + 1];
            int sj2 = s_src[warp][j + 2];
            int sj3 = s_src[warp][j + 3];
            uint2 r0 = *(const uint2*)&hh[sj0 * HD + lane * 4];
            uint2 r1 = *(const uint2*)&hh[sj1 * HD + lane * 4];
            uint2 r2 = *(const uint2*)&hh[sj2 * HD + lane * 4];
            uint2 r3 = *(const uint2*)&hh[sj3 * HD + lane * 4];
            float a0 = s_alpha[warp][j + 0][myh];
            float a1 = s_alpha[warp][j + 1][myh];
            float a2 = s_alpha[warp][j + 2][myh];
            float a3 = s_alpha[warp][j + 3][myh];
            float2 f;
            f = __half22float2(*(const __half2*)&r0.x); acc.x = fmaf(a0, f.x, acc.x); acc.y = fmaf(a0, f.y, acc.y);
            f = __half22float2(*(const __half2*)&r0.y); acc.z = fmaf(a0, f.x, acc.z); acc.w = fmaf(a0, f.y, acc.w);
            f = __half22float2(*(const __half2*)&r1.x); acc.x = fmaf(a1, f.x, acc.x); acc.y = fmaf(a1, f.y, acc.y);
            f = __half22float2(*(const __half2*)&r1.y); acc.z = fmaf(a1, f.x, acc.z); acc.w = fmaf(a1, f.y, acc.w);
            f = __half22float2(*(const __half2*)&r2.x); acc.x = fmaf(a2, f.x, acc.x); acc.y = fmaf(a2, f.y, acc.y);
            f = __half22float2(*(const __half2*)&r2.y); acc.z = fmaf(a2, f.x, acc.z); acc.w = fmaf(a2, f.y, acc.w);
            f = __half22float2(*(const __half2*)&r3.x); acc.x = fmaf(a3, f.x, acc.x); acc.y = fmaf(a3, f.y, acc.y);
            f = __half22float2(*(const __half2*)&r3.y); acc.z = fmaf(a3, f.x, acc.z); acc.w = fmaf(a3, f.y, acc.w);
        }
        for (; j < nb; j++) {
            int sj = s_src[warp][j];
            float a = s_alpha[warp][j][myh];
            uint2 r = *(const uint2*)&hh[sj * HD + lane * 4];
            float2 f01 = __half22float2(*(const __half2*)&r.x);
            float2 f23 = __half22float2(*(const __half2*)&r.y);
            acc.x = fmaf(a, f01.x, acc.x);
            acc.y = fmaf(a, f01.y, acc.y);
            acc.z = fmaf(a, f23.x, acc.z);
            acc.w = fmaf(a, f23.y, acc.w);
        }
        __syncwarp();
    }

    // reduce over heads
    acc.x += __shfl_xor_sync(0xffffffffu, acc.x, 8);
    acc.y += __shfl_xor_sync(0xffffffffu, acc.y, 8);
    acc.z += __shfl_xor_sync(0xffffffffu, acc.z, 8);
    acc.w += __shfl_xor_sync(0xffffffffu, acc.w, 8);
    acc.x += __shfl_xor_sync(0xffffffffu, acc.x, 16);
    acc.y += __shfl_xor_sync(0xffffffffu, acc.y, 16);
    acc.z += __shfl_xor_sync(0xffffffffu, acc.z, 16);
    acc.w += __shfl_xor_sync(0xffffffffu, acc.w, 16);

    if (lane < 8) {
        float4 b4 = *(const float4*)&bias[lane * 4];
        float4 o;
        o.x = acc.x * 0.25f + b4.x;
        o.y = acc.y * 0.25f + b4.y;
        o.z = acc.z * 0.25f + b4.z;
        o.w = acc.w * 0.25f + b4.w;
        *(float4*)&out[n * OUT_DIM + lane * 4] = o;
    }
}

// ---------------- launch: 6 kernels; index 3 (k_gemm) is the profiled one ----------------
extern "C" void kernel_launch(void* const* d_in, const int* in_sizes, int n_in,
                              void* d_out, int out_size) {
    const float* x    = (const float*)d_in[0];
    const int*   ei   = (const int*)  d_in[1];
    const float* ea   = (const float*)d_in[2];
    const float* Wl   = (const float*)d_in[3];
    const float* as   = (const float*)d_in[4];
    const float* ad   = (const float*)d_in[5];
    const float* bias = (const float*)d_in[6];
    const float* We   = (const float*)d_in[7];
    float* out = (float*)d_out;

    k_hist  <<<(N_EDGES / 4 + 255) / 256, 256>>>(ei);
    k_transW<<<16, 256>>>(Wl);
    k_scan  <<<98, 512>>>();
    k_gemm  <<<(N_NODES + 127) / 128, 256>>>(x, as, ad);
    k_edge  <<<(N_EDGES + 511) / 512, 256>>>(ei, ea, We);
    k_agg   <<<(N_NODES + 7) / 8, 256>>>(bias, out);
}

// round 13
// speedup vs baseline: 1.7598x; 1.0736x over previous
#include <cuda_runtime.h>
#include <cuda_fp16.h>

#define N_NODES 50000
#define N_EDGES 1600000
#define IN_DIM 128
#define OUT_DIM 32
#define HEADS 4
#define HD 128           // HEADS * OUT_DIM
#define EDGE_DIM 16

// ---------------- device scratch (static: no allocation allowed) ----------------
// g_cnt invariant: all-zero at kernel_launch entry. First call: .bss zero-init.
// Every call: k_edge re-zeroes it (after k_scan consumed it, before next call's k_hist).
__device__ __half g_hh[N_NODES * HD];         // 12.8 MB  h (fp16)
__device__ unsigned g_Wfrag[8 * 16 * 32 * 2]; // 16 KB: B fragments [kstep][ntile][lane][2]
__device__ float g_asrc[N_NODES * HEADS];
__device__ float g_adst[N_NODES * HEADS];
__device__ int   g_cnt[N_NODES];
__device__ int   g_off[N_NODES + 1];
__device__ int   g_rank[N_EDGES];             // rank of edge within its dst segment
__device__ uint4 g_csr[N_EDGES];              // 25.6 MB: {src, exp01(h2), exp23(h2), pad}

// ---------------- hist: 8 edges/thread for MLP ----------------
__global__ void k_hist(const int* __restrict__ ei) {
    int i = blockIdx.x * blockDim.x + threadIdx.x;
    if (i < N_EDGES / 8) {
        const int4* dp = (const int4*)(ei + N_EDGES);
        int4 d0 = dp[2 * i];
        int4 d1 = dp[2 * i + 1];
        int4 r0, r1;
        r0.x = atomicAdd(&g_cnt[d0.x], 1);
        r0.y = atomicAdd(&g_cnt[d0.y], 1);
        r0.z = atomicAdd(&g_cnt[d0.z], 1);
        r0.w = atomicAdd(&g_cnt[d0.w], 1);
        r1.x = atomicAdd(&g_cnt[d1.x], 1);
        r1.y = atomicAdd(&g_cnt[d1.y], 1);
        r1.z = atomicAdd(&g_cnt[d1.z], 1);
        r1.w = atomicAdd(&g_cnt[d1.w], 1);
        ((int4*)g_rank)[2 * i]     = r0;
        ((int4*)g_rank)[2 * i + 1] = r1;
    }
}

// ---------------- scan (+ fused W fragment pack in blocks 0..7) ----------------
// transW: lane l (q=l&3, g=l>>2) of tile (kstep s, ntile t): b0 = W[t*8+g][s*16+2q..+1],
// b1 = W[t*8+g][s*16+2q+8..+9].
__global__ __launch_bounds__(512) void k_scan(const float* __restrict__ W) {
    __shared__ int sh[512];
    int b = blockIdx.x, t = threadIdx.x;

    if (b < 8) {
        int i = b * 512 + t;             // 0..4095
        int l = i & 31;
        int tt = (i >> 5) & 15;
        int s = i >> 9;
        int q = l & 3, g = l >> 2;
        int j = tt * 8 + g;
        int k0 = s * 16 + 2 * q;
        float w00 = W[j * IN_DIM + k0];
        float w01 = W[j * IN_DIM + k0 + 1];
        float w10 = W[j * IN_DIM + k0 + 8];
        float w11 = W[j * IN_DIM + k0 + 9];
        __half2 b0 = __floats2half2_rn(w00, w01);
        __half2 b1 = __floats2half2_rn(w10, w11);
        uint2 o;
        o.x = *(unsigned*)&b0;
        o.y = *(unsigned*)&b1;
        ((uint2*)g_Wfrag)[i] = o;
    }

    int base = b * 512;
    int s = 0;
    for (int i = t; i < base; i += 512) s += g_cnt[i];
    sh[t] = s;
    __syncthreads();
    for (int off = 256; off > 0; off >>= 1) {
        if (t < off) sh[t] += sh[t + off];
        __syncthreads();
    }
    int pre = sh[0];
    __syncthreads();

    int idx = base + t;
    int c = (idx < N_NODES) ? g_cnt[idx] : 0;
    sh[t] = c;
    __syncthreads();
    for (int off = 1; off < 512; off <<= 1) {
        int u = (t >= off) ? sh[t - off] : 0;
        __syncthreads();
        sh[t] += u;
        __syncthreads();
    }
    if (idx < N_NODES) g_off[idx] = pre + sh[t] - c;
    if (b == 0 && t == 0) g_off[N_NODES] = N_EDGES;
}

// ---------------- GEMM: h = x@W^T via mma.sync m16n8k16 (fp16 in, fp32 acc) ----------------
__global__ __launch_bounds__(256) void k_gemm(const float* __restrict__ x,
                                              const float* __restrict__ att_src,
                                              const float* __restrict__ att_dst) {
    __shared__ __align__(16) __half sh[128 * 136];   // x tile, later h staging

    int tid = threadIdx.x;
    int n0 = blockIdx.x * 128;
    int warp = tid >> 5, lane = tid & 31;
    int wm = warp & 3;
    int wn = warp >> 2;
    int q = lane & 3, g = lane >> 2;

    // load + convert x tile: 128 rows x 32 float4s = 4096
#pragma unroll
    for (int r = 0; r < 16; r++) {
        int uidx = r * 256 + tid;
        int row = uidx >> 5, c4 = uidx & 31;
        int gn = n0 + row;
        float4 v = {0.f, 0.f, 0.f, 0.f};
        if (gn < N_NODES) v = *(const float4*)&x[gn * IN_DIM + c4 * 4];
        __half2 p0 = __floats2half2_rn(v.x, v.y);
        __half2 p1 = __floats2half2_rn(v.z, v.w);
        uint2 pk;
        pk.x = *(unsigned*)&p0;
        pk.y = *(unsigned*)&p1;
        *(uint2*)&sh[row * 136 + c4 * 4] = pk;
    }
    __syncthreads();

    float acc[2][8][4];
#pragma unroll
    for (int m = 0; m < 2; m++)
#pragma unroll
        for (int nt = 0; nt < 8; nt++)
#pragma unroll
            for (int c = 0; c < 4; c++) acc[m][nt][c] = 0.f;

    const uint2* wf = (const uint2*)g_Wfrag;
    for (int s = 0; s < 8; s++) {
        unsigned a[2][4];
#pragma unroll
        for (int m = 0; m < 2; m++) {
            int r0 = wm * 32 + m * 16 + g;
            int c0 = s * 16 + 2 * q;
            a[m][0] = *(const unsigned*)&sh[r0 * 136 + c0];
            a[m][1] = *(const unsigned*)&sh[(r0 + 8) * 136 + c0];
            a[m][2] = *(const unsigned*)&sh[r0 * 136 + c0 + 8];
            a[m][3] = *(const unsigned*)&sh[(r0 + 8) * 136 + c0 + 8];
        }
#pragma unroll
        for (int nt = 0; nt < 8; nt++) {
            uint2 b = wf[(s * 16 + wn * 8 + nt) * 32 + lane];
#pragma unroll
            for (int m = 0; m < 2; m++) {
                asm volatile(
                    "mma.sync.aligned.m16n8k16.row.col.f32.f16.f16.f32 "
                    "{%0,%1,%2,%3}, {%4,%5,%6,%7}, {%8,%9}, {%0,%1,%2,%3};"
                    : "+f"(acc[m][nt][0]), "+f"(acc[m][nt][1]),
                      "+f"(acc[m][nt][2]), "+f"(acc[m][nt][3])
                    : "r"(a[m][0]), "r"(a[m][1]), "r"(a[m][2]), "r"(a[m][3]),
                      "r"(b.x), "r"(b.y));
            }
        }
    }

    // fused a_src/a_dst from fp32 fragments
    float2 as2[8], ad2[8];
#pragma unroll
    for (int nt = 0; nt < 8; nt++) {
        int j = wn * 64 + nt * 8 + 2 * q;
        as2[nt] = *(const float2*)&att_src[j];
        ad2[nt] = *(const float2*)&att_dst[j];
    }
#pragma unroll
    for (int m = 0; m < 2; m++) {
        float v[8] = {0.f, 0.f, 0.f, 0.f, 0.f, 0.f, 0.f, 0.f};
#pragma unroll
        for (int nt = 0; nt < 8; nt++) {
            int hsel = (nt >> 2);
            float ax0 = acc[m][nt][0], ax1 = acc[m][nt][1];
            float ay0 = acc[m][nt][2], ay1 = acc[m][nt][3];
            v[0 + hsel] += ax0 * as2[nt].x + ax1 * as2[nt].y;
            v[2 + hsel] += ax0 * ad2[nt].x + ax1 * ad2[nt].y;
            v[4 + hsel] += ay0 * as2[nt].x + ay1 * as2[nt].y;
            v[6 + hsel] += ay0 * ad2[nt].x + ay1 * ad2[nt].y;
        }
#pragma unroll
        for (int k = 0; k < 8; k++) {
            v[k] += __shfl_xor_sync(0xffffffffu, v[k], 1);
            v[k] += __shfl_xor_sync(0xffffffffu, v[k], 2);
        }
        if (q == 0) {
            int node0 = n0 + wm * 32 + m * 16 + g;
            int node1 = node0 + 8;
            if (node0 < N_NODES) {
                g_asrc[node0 * 4 + wn * 2 + 0] = v[0];
                g_asrc[node0 * 4 + wn * 2 + 1] = v[1];
                g_adst[node0 * 4 + wn * 2 + 0] = v[2];
                g_adst[node0 * 4 + wn * 2 + 1] = v[3];
            }
            if (node1 < N_NODES) {
                g_asrc[node1 * 4 + wn * 2 + 0] = v[4];
                g_asrc[node1 * 4 + wn * 2 + 1] = v[5];
                g_adst[node1 * 4 + wn * 2 + 0] = v[6];
                g_adst[node1 * 4 + wn * 2 + 1] = v[7];
            }
        }
    }

    // stage h (fp16) into smem, then coalesced global write
    __syncthreads();
#pragma unroll
    for (int m = 0; m < 2; m++) {
        int r0 = wm * 32 + m * 16 + g;
#pragma unroll
        for (int nt = 0; nt < 8; nt++) {
            int col = wn * 64 + nt * 8 + 2 * q;
            __half2 h0 = __floats2half2_rn(acc[m][nt][0], acc[m][nt][1]);
            __half2 h1 = __floats2half2_rn(acc[m][nt][2], acc[m][nt][3]);
            *(unsigned*)&sh[r0 * 136 + col] = *(unsigned*)&h0;
            *(unsigned*)&sh[(r0 + 8) * 136 + col] = *(unsigned*)&h1;
        }
    }
    __syncthreads();
#pragma unroll
    for (int r = 0; r < 8; r++) {
        int uidx = r * 256 + tid;
        int row = uidx >> 4, c16 = uidx & 15;
        int gn = n0 + row;
        if (gn < N_NODES) {
            uint4 vv = *(const uint4*)&sh[row * 136 + c16 * 8];
            *(uint4*)&g_hh[gn * HD + c16 * 8] = vv;
        }
    }
}

// ---------------- edge pass: 2 edges/thread, phase-separated loads, no bounds checks ----
// 1600000 = 3125 blocks * 512 edges exactly.
__global__ __launch_bounds__(256) void k_edge(const int* __restrict__ ei,
                                              const float* __restrict__ ea,
                                              const float* __restrict__ Wedge) {
    __shared__ float we[HEADS * EDGE_DIM];
    if (threadIdx.x < HEADS * EDGE_DIM) we[threadIdx.x] = Wedge[threadIdx.x];
    __syncthreads();

    int gidx = blockIdx.x * blockDim.x + threadIdx.x;
    // reset g_cnt for the NEXT launch (scan already consumed it this launch)
    if (gidx < N_NODES) g_cnt[gidx] = 0;

    int eA = blockIdx.x * 512 + threadIdx.x;
    int eB = eA + 256;

    // ---- load phase: all independent loads in flight ----
    int srcA = ei[eA];
    int srcB = ei[eB];
    int dstA = ei[N_EDGES + eA];
    int dstB = ei[N_EDGES + eB];

    const float4* epA = (const float4*)&ea[eA * EDGE_DIM];
    const float4* epB = (const float4*)&ea[eB * EDGE_DIM];
    float4 qa0 = epA[0], qa1 = epA[1], qa2 = epA[2], qa3 = epA[3];
    float4 qb0 = epB[0], qb1 = epB[1], qb2 = epB[2], qb3 = epB[3];

    float4 aA = *(const float4*)&g_asrc[srcA * 4];
    float4 aB = *(const float4*)&g_asrc[srcB * 4];
    float4 bA = *(const float4*)&g_adst[dstA * 4];
    float4 bB = *(const float4*)&g_adst[dstB * 4];
    int rkA = g_rank[eA];
    int rkB = g_rank[eB];
    int ofA = g_off[dstA];
    int ofB = g_off[dstB];

    // ---- compute phase ----
    float evA[16] = {qa0.x, qa0.y, qa0.z, qa0.w, qa1.x, qa1.y, qa1.z, qa1.w,
                     qa2.x, qa2.y, qa2.z, qa2.w, qa3.x, qa3.y, qa3.z, qa3.w};
    float evB[16] = {qb0.x, qb0.y, qb0.z, qb0.w, qb1.x, qb1.y, qb1.z, qb1.w,
                     qb2.x, qb2.y, qb2.z, qb2.w, qb3.x, qb3.y, qb3.z, qb3.w};

    float lgA[4], lgB[4];
#pragma unroll
    for (int h = 0; h < 4; h++) {
        float sA = 0.f, sB = 0.f;
#pragma unroll
        for (int k = 0; k < 16; k++) {
            float w = we[h * 16 + k];
            sA = fmaf(evA[k], w, sA);
            sB = fmaf(evB[k], w, sB);
        }
        lgA[h] = sA;
        lgB[h] = sB;
    }
    lgA[0] += aA.x + bA.x;  lgA[1] += aA.y + bA.y;
    lgA[2] += aA.z + bA.z;  lgA[3] += aA.w + bA.w;
    lgB[0] += aB.x + bB.x;  lgB[1] += aB.y + bB.y;
    lgB[2] += aB.z + bB.z;  lgB[3] += aB.w + bB.w;
#pragma unroll
    for (int h = 0; h < 4; h++) {
        float vA = (lgA[h] > 0.f) ? lgA[h] : 0.2f * lgA[h];
        float vB = (lgB[h] > 0.f) ? lgB[h] : 0.2f * lgB[h];
        lgA[h] = __expf(vA);
        lgB[h] = __expf(vB);
    }

    // ---- store phase ----
    {
        __half2 x01 = __floats2half2_rn(lgA[0], lgA[1]);
        __half2 x23 = __floats2half2_rn(lgA[2], lgA[3]);
        uint4 rec;
        rec.x = (unsigned)srcA;
        rec.y = *(const unsigned*)&x01;
        rec.z = *(const unsigned*)&x23;
        rec.w = 0u;
        g_csr[ofA + rkA] = rec;
    }
    {
        __half2 x01 = __floats2half2_rn(lgB[0], lgB[1]);
        __half2 x23 = __floats2half2_rn(lgB[2], lgB[3]);
        uint4 rec;
        rec.x = (unsigned)srcB;
        rec.y = *(const unsigned*)&x01;
        rec.z = *(const unsigned*)&x23;
        rec.w = 0u;
        g_csr[ofB + rkB] = rec;
    }
}

// ---------------- aggregation: warp per node, 8-wide MLP fp16 gather ----------------
__global__ __launch_bounds__(256) void k_agg(const float* __restrict__ bias,
                                             float* __restrict__ out) {
    __shared__ float s_alpha[8][32][4];
    __shared__ int   s_src[8][32];

    int warp = threadIdx.x >> 5;
    int lane = threadIdx.x & 31;
    int n = blockIdx.x * 8 + warp;
    if (n >= N_NODES) return;

    int beg = g_off[n];
    int end = g_off[n + 1];
    int myh = lane >> 3;

    // pass 1: denom per head
    float d0 = 0.f, d1 = 0.f, d2 = 0.f, d3 = 0.f;
    for (int i = beg + lane; i < end; i += 32) {
        uint4 r = g_csr[i];
        float2 f01 = __half22float2(*(const __half2*)&r.y);
        float2 f23 = __half22float2(*(const __half2*)&r.z);
        d0 += f01.x; d1 += f01.y; d2 += f23.x; d3 += f23.y;
    }
#pragma unroll
    for (int off = 16; off > 0; off >>= 1) {
        d0 += __shfl_xor_sync(0xffffffffu, d0, off);
        d1 += __shfl_xor_sync(0xffffffffu, d1, off);
        d2 += __shfl_xor_sync(0xffffffffu, d2, off);
        d3 += __shfl_xor_sync(0xffffffffu, d3, off);
    }
    float i0 = 1.f / (d0 + 1e-16f);
    float i1 = 1.f / (d1 + 1e-16f);
    float i2 = 1.f / (d2 + 1e-16f);
    float i3 = 1.f / (d3 + 1e-16f);

    // pass 2: alpha-weighted gather of h[src], 8 loads in flight
    float4 acc = {0.f, 0.f, 0.f, 0.f};
    const __half* hh = g_hh;
    for (int c = beg; c < end; c += 32) {
        int i = c + lane;
        int nb = min(32, end - c);
        if (lane < nb) {
            uint4 r = g_csr[i];
            float2 f01 = __half22float2(*(const __half2*)&r.y);
            float2 f23 = __half22float2(*(const __half2*)&r.z);
            s_src[warp][lane] = (int)r.x;
            s_alpha[warp][lane][0] = f01.x * i0;
            s_alpha[warp][lane][1] = f01.y * i1;
            s_alpha[warp][lane][2] = f23.x * i2;
            s_alpha[warp][lane][3] = f23.y * i3;
        }
        __syncwarp();
        int j = 0;
        for (; j + 8 <= nb; j += 8) {
            uint2 rr[8];
            float aa[8];
#pragma unroll
            for (int u = 0; u < 8; u++) {
                int sj = s_src[warp][j + u];
                rr[u] = *(const uint2*)&hh[sj * HD + lane * 4];
                aa[u] = s_alpha[warp][j + u][myh];
            }
#pragma unroll
            for (int u = 0; u < 8; u++) {
                float2 f01 = __half22float2(*(const __half2*)&rr[u].x);
                float2 f23 = __half22float2(*(const __half2*)&rr[u].y);
                acc.x = fmaf(aa[u], f01.x, acc.x);
                acc.y = fmaf(aa[u], f01.y, acc.y);
                acc.z = fmaf(aa[u], f23.x, acc.z);
                acc.w = fmaf(aa[u], f23.y, acc.w);
            }
        }
        for (; j < nb; j++) {
            int sj = s_src[warp][j];
            float a = s_alpha[warp][j][myh];
            uint2 r = *(const uint2*)&hh[sj * HD + lane * 4];
            float2 f01 = __half22float2(*(const __half2*)&r.x);
            float2 f23 = __half22float2(*(const __half2*)&r.y);
            acc.x = fmaf(a, f01.x, acc.x);
            acc.y = fmaf(a, f01.y, acc.y);
            acc.z = fmaf(a, f23.x, acc.z);
            acc.w = fmaf(a, f23.y, acc.w);
        }
        __syncwarp();
    }

    // reduce over heads
    acc.x += __shfl_xor_sync(0xffffffffu, acc.x, 8);
    acc.y += __shfl_xor_sync(0xffffffffu, acc.y, 8);
    acc.z += __shfl_xor_sync(0xffffffffu, acc.z, 8);
    acc.w += __shfl_xor_sync(0xffffffffu, acc.w, 8);
    acc.x += __shfl_xor_sync(0xffffffffu, acc.x, 16);
    acc.y += __shfl_xor_sync(0xffffffffu, acc.y, 16);
    acc.z += __shfl_xor_sync(0xffffffffu, acc.z, 16);
    acc.w += __shfl_xor_sync(0xffffffffu, acc.w, 16);

    if (lane < 8) {
        float4 b4 = *(const float4*)&bias[lane * 4];
        float4 o;
        o.x = acc.x * 0.25f + b4.x;
        o.y = acc.y * 0.25f + b4.y;
        o.z = acc.z * 0.25f + b4.z;
        o.w = acc.w * 0.25f + b4.w;
        *(float4*)&out[n * OUT_DIM + lane * 4] = o;
    }
}

// ---------------- launch: 5 kernels; index 3 (k_edge) is the profiled one ----------------
extern "C" void kernel_launch(void* const* d_in, const int* in_sizes, int n_in,
                              void* d_out, int out_size) {
    const float* x    = (const float*)d_in[0];
    const int*   ei   = (const int*)  d_in[1];
    const float* ea   = (const float*)d_in[2];
    const float* Wl   = (const float*)d_in[3];
    const float* as   = (const float*)d_in[4];
    const float* ad   = (const float*)d_in[5];
    const float* bias = (const float*)d_in[6];
    const float* We   = (const float*)d_in[7];
    float* out = (float*)d_out;

    k_hist <<<(N_EDGES / 8 + 255) / 256, 256>>>(ei);
    k_scan <<<98, 512>>>(Wl);
    k_gemm <<<(N_NODES + 127) / 128, 256>>>(x, as, ad);
    k_edge <<<3125, 256>>>(ei, ea, We);
    k_agg  <<<(N_NODES + 7) / 8, 256>>>(bias, out);
}

// round 14
// speedup vs baseline: 1.9035x; 1.0817x over previous
#include <cuda_runtime.h>
#include <cuda_fp16.h>

#define N_NODES 50000
#define N_EDGES 1600000
#define IN_DIM 128
#define OUT_DIM 32
#define HEADS 4
#define HD 128           // HEADS * OUT_DIM
#define EDGE_DIM 16

// ---------------- device scratch (static: no allocation allowed) ----------------
// g_cnt invariant: all-zero at kernel_launch entry. First call: .bss zero-init.
// Every call: k_edge re-zeroes it (after the scan consumed it, before next call's k_hist).
__device__ __half g_hh[N_NODES * HD];         // 12.8 MB  h (fp16)
__device__ unsigned g_Wfrag[8 * 16 * 32 * 2]; // 16 KB: B fragments [kstep][ntile][lane][2]
__device__ float g_asrc[N_NODES * HEADS];
__device__ float g_adst[N_NODES * HEADS];
__device__ int   g_cnt[N_NODES];
__device__ int   g_off[N_NODES + 1];
__device__ int   g_rank[N_EDGES];             // rank of edge within its dst segment
__device__ uint4 g_csr[N_EDGES];              // 25.6 MB: {src, exp01(h2), exp23(h2), pad}

// ---------------- hist: 8 edges/thread + fused W-fragment pack (blocks 0..15) ----------
// W-pack: lane l (q=l&3, g=l>>2) of tile (kstep s, ntile t): b0 = W[t*8+g][s*16+2q..+1],
// b1 = W[t*8+g][s*16+2q+8..+9]  (for mma.m16n8k16.row.col B operand).
__global__ void k_hist(const int* __restrict__ ei, const float* __restrict__ W) {
    int i = blockIdx.x * blockDim.x + threadIdx.x;

    if (i < 4096) {   // blocks 0..15: pack W fragments (independent of hist work)
        int l = i & 31;
        int tt = (i >> 5) & 15;
        int s = i >> 9;
        int q = l & 3, g = l >> 2;
        int j = tt * 8 + g;
        int k0 = s * 16 + 2 * q;
        float w00 = W[j * IN_DIM + k0];
        float w01 = W[j * IN_DIM + k0 + 1];
        float w10 = W[j * IN_DIM + k0 + 8];
        float w11 = W[j * IN_DIM + k0 + 9];
        __half2 b0 = __floats2half2_rn(w00, w01);
        __half2 b1 = __floats2half2_rn(w10, w11);
        uint2 o;
        o.x = *(unsigned*)&b0;
        o.y = *(unsigned*)&b1;
        ((uint2*)g_Wfrag)[i] = o;
    }

    if (i < N_EDGES / 8) {
        const int4* dp = (const int4*)(ei + N_EDGES);
        int4 d0 = dp[2 * i];
        int4 d1 = dp[2 * i + 1];
        int4 r0, r1;
        r0.x = atomicAdd(&g_cnt[d0.x], 1);
        r0.y = atomicAdd(&g_cnt[d0.y], 1);
        r0.z = atomicAdd(&g_cnt[d0.z], 1);
        r0.w = atomicAdd(&g_cnt[d0.w], 1);
        r1.x = atomicAdd(&g_cnt[d1.x], 1);
        r1.y = atomicAdd(&g_cnt[d1.y], 1);
        r1.z = atomicAdd(&g_cnt[d1.z], 1);
        r1.w = atomicAdd(&g_cnt[d1.w], 1);
        ((int4*)g_rank)[2 * i]     = r0;
        ((int4*)g_rank)[2 * i + 1] = r1;
    }
}

// ---------------- fused scan (blocks 0..97) + GEMM (blocks 98..488) ----------------
// Scan: redundant-prefix, 256 threads, 512 nodes/block (2 per thread).
// GEMM: h = x@W^T via mma.sync m16n8k16 (fp16 in, fp32 acc), fused a_src/a_dst.
__global__ __launch_bounds__(256) void k_sgemm(const float* __restrict__ x,
                                               const float* __restrict__ att_src,
                                               const float* __restrict__ att_dst) {
    __shared__ __align__(16) __half sh[128 * 136];   // gemm: x tile, later h staging
    __shared__ int shi[256];                          // scan workspace

    int tid = threadIdx.x;
    int b = blockIdx.x;

    if (b < 98) {
        // ---------------- scan block ----------------
        int base = b * 512;
        int s = 0;
        for (int i = tid; i < base; i += 256) s += g_cnt[i];
        shi[tid] = s;
        __syncthreads();
        for (int off = 128; off > 0; off >>= 1) {
            if (tid < off) shi[tid] += shi[tid + off];
            __syncthreads();
        }
        int pre = shi[0];
        __syncthreads();

        int i0 = base + 2 * tid, i1 = i0 + 1;
        int c0 = (i0 < N_NODES) ? g_cnt[i0] : 0;
        int c1 = (i1 < N_NODES) ? g_cnt[i1] : 0;
        int mys = c0 + c1;
        shi[tid] = mys;
        __syncthreads();
        for (int off = 1; off < 256; off <<= 1) {
            int u = (tid >= off) ? shi[tid - off] : 0;
            __syncthreads();
            shi[tid] += u;
            __syncthreads();
        }
        int excl = shi[tid] - mys + pre;
        if (i0 < N_NODES) g_off[i0] = excl;
        if (i1 < N_NODES) g_off[i1] = excl + c0;
        if (b == 0 && tid == 0) g_off[N_NODES] = N_EDGES;
        return;
    }

    // ---------------- gemm block ----------------
    int n0 = (b - 98) * 128;
    int warp = tid >> 5, lane = tid & 31;
    int wm = warp & 3;
    int wn = warp >> 2;
    int q = lane & 3, g = lane >> 2;

    // load + convert x tile: 128 rows x 32 float4s = 4096
#pragma unroll
    for (int r = 0; r < 16; r++) {
        int uidx = r * 256 + tid;
        int row = uidx >> 5, c4 = uidx & 31;
        int gn = n0 + row;
        float4 v = {0.f, 0.f, 0.f, 0.f};
        if (gn < N_NODES) v = *(const float4*)&x[gn * IN_DIM + c4 * 4];
        __half2 p0 = __floats2half2_rn(v.x, v.y);
        __half2 p1 = __floats2half2_rn(v.z, v.w);
        uint2 pk;
        pk.x = *(unsigned*)&p0;
        pk.y = *(unsigned*)&p1;
        *(uint2*)&sh[row * 136 + c4 * 4] = pk;
    }
    __syncthreads();

    float acc[2][8][4];
#pragma unroll
    for (int m = 0; m < 2; m++)
#pragma unroll
        for (int nt = 0; nt < 8; nt++)
#pragma unroll
            for (int c = 0; c < 4; c++) acc[m][nt][c] = 0.f;

    const uint2* wf = (const uint2*)g_Wfrag;
    for (int s = 0; s < 8; s++) {
        unsigned a[2][4];
#pragma unroll
        for (int m = 0; m < 2; m++) {
            int r0 = wm * 32 + m * 16 + g;
            int c0 = s * 16 + 2 * q;
            a[m][0] = *(const unsigned*)&sh[r0 * 136 + c0];
            a[m][1] = *(const unsigned*)&sh[(r0 + 8) * 136 + c0];
            a[m][2] = *(const unsigned*)&sh[r0 * 136 + c0 + 8];
            a[m][3] = *(const unsigned*)&sh[(r0 + 8) * 136 + c0 + 8];
        }
#pragma unroll
        for (int nt = 0; nt < 8; nt++) {
            uint2 bb = wf[(s * 16 + wn * 8 + nt) * 32 + lane];
#pragma unroll
            for (int m = 0; m < 2; m++) {
                asm volatile(
                    "mma.sync.aligned.m16n8k16.row.col.f32.f16.f16.f32 "
                    "{%0,%1,%2,%3}, {%4,%5,%6,%7}, {%8,%9}, {%0,%1,%2,%3};"
                    : "+f"(acc[m][nt][0]), "+f"(acc[m][nt][1]),
                      "+f"(acc[m][nt][2]), "+f"(acc[m][nt][3])
                    : "r"(a[m][0]), "r"(a[m][1]), "r"(a[m][2]), "r"(a[m][3]),
                      "r"(bb.x), "r"(bb.y));
            }
        }
    }

    // fused a_src/a_dst from fp32 fragments
    float2 as2[8], ad2[8];
#pragma unroll
    for (int nt = 0; nt < 8; nt++) {
        int j = wn * 64 + nt * 8 + 2 * q;
        as2[nt] = *(const float2*)&att_src[j];
        ad2[nt] = *(const float2*)&att_dst[j];
    }
#pragma unroll
    for (int m = 0; m < 2; m++) {
        float v[8] = {0.f, 0.f, 0.f, 0.f, 0.f, 0.f, 0.f, 0.f};
#pragma unroll
        for (int nt = 0; nt < 8; nt++) {
            int hsel = (nt >> 2);
            float ax0 = acc[m][nt][0], ax1 = acc[m][nt][1];
            float ay0 = acc[m][nt][2], ay1 = acc[m][nt][3];
            v[0 + hsel] += ax0 * as2[nt].x + ax1 * as2[nt].y;
            v[2 + hsel] += ax0 * ad2[nt].x + ax1 * ad2[nt].y;
            v[4 + hsel] += ay0 * as2[nt].x + ay1 * as2[nt].y;
            v[6 + hsel] += ay0 * ad2[nt].x + ay1 * ad2[nt].y;
        }
#pragma unroll
        for (int k = 0; k < 8; k++) {
            v[k] += __shfl_xor_sync(0xffffffffu, v[k], 1);
            v[k] += __shfl_xor_sync(0xffffffffu, v[k], 2);
        }
        if (q == 0) {
            int node0 = n0 + wm * 32 + m * 16 + g;
            int node1 = node0 + 8;
            if (node0 < N_NODES) {
                g_asrc[node0 * 4 + wn * 2 + 0] = v[0];
                g_asrc[node0 * 4 + wn * 2 + 1] = v[1];
                g_adst[node0 * 4 + wn * 2 + 0] = v[2];
                g_adst[node0 * 4 + wn * 2 + 1] = v[3];
            }
            if (node1 < N_NODES) {
                g_asrc[node1 * 4 + wn * 2 + 0] = v[4];
                g_asrc[node1 * 4 + wn * 2 + 1] = v[5];
                g_adst[node1 * 4 + wn * 2 + 0] = v[6];
                g_adst[node1 * 4 + wn * 2 + 1] = v[7];
            }
        }
    }

    // stage h (fp16) into smem, then coalesced global write
    __syncthreads();
#pragma unroll
    for (int m = 0; m < 2; m++) {
        int r0 = wm * 32 + m * 16 + g;
#pragma unroll
        for (int nt = 0; nt < 8; nt++) {
            int col = wn * 64 + nt * 8 + 2 * q;
            __half2 h0 = __floats2half2_rn(acc[m][nt][0], acc[m][nt][1]);
            __half2 h1 = __floats2half2_rn(acc[m][nt][2], acc[m][nt][3]);
            *(unsigned*)&sh[r0 * 136 + col] = *(unsigned*)&h0;
            *(unsigned*)&sh[(r0 + 8) * 136 + col] = *(unsigned*)&h1;
        }
    }
    __syncthreads();
#pragma unroll
    for (int r = 0; r < 8; r++) {
        int uidx = r * 256 + tid;
        int row = uidx >> 4, c16 = uidx & 15;
        int gn = n0 + row;
        if (gn < N_NODES) {
            uint4 vv = *(const uint4*)&sh[row * 136 + c16 * 8];
            *(uint4*)&g_hh[gn * HD + c16 * 8] = vv;
        }
    }
}

// ---------------- edge pass: 2 edges/thread, phase-separated loads ----------------
// 1600000 = 3125 blocks * 512 edges exactly.
__global__ __launch_bounds__(256) void k_edge(const int* __restrict__ ei,
                                              const float* __restrict__ ea,
                                              const float* __restrict__ Wedge) {
    __shared__ float we[HEADS * EDGE_DIM];
    if (threadIdx.x < HEADS * EDGE_DIM) we[threadIdx.x] = Wedge[threadIdx.x];
    __syncthreads();

    int gidx = blockIdx.x * blockDim.x + threadIdx.x;
    // reset g_cnt for the NEXT launch (scan already consumed it this launch)
    if (gidx < N_NODES) g_cnt[gidx] = 0;

    int eA = blockIdx.x * 512 + threadIdx.x;
    int eB = eA + 256;

    // ---- load phase ----
    int srcA = ei[eA];
    int srcB = ei[eB];
    int dstA = ei[N_EDGES + eA];
    int dstB = ei[N_EDGES + eB];

    const float4* epA = (const float4*)&ea[eA * EDGE_DIM];
    const float4* epB = (const float4*)&ea[eB * EDGE_DIM];
    float4 qa0 = epA[0], qa1 = epA[1], qa2 = epA[2], qa3 = epA[3];
    float4 qb0 = epB[0], qb1 = epB[1], qb2 = epB[2], qb3 = epB[3];

    float4 aA = *(const float4*)&g_asrc[srcA * 4];
    float4 aB = *(const float4*)&g_asrc[srcB * 4];
    float4 bA = *(const float4*)&g_adst[dstA * 4];
    float4 bB = *(const float4*)&g_adst[dstB * 4];
    int rkA = g_rank[eA];
    int rkB = g_rank[eB];
    int ofA = g_off[dstA];
    int ofB = g_off[dstB];

    // ---- compute phase ----
    float evA[16] = {qa0.x, qa0.y, qa0.z, qa0.w, qa1.x, qa1.y, qa1.z, qa1.w,
                     qa2.x, qa2.y, qa2.z, qa2.w, qa3.x, qa3.y, qa3.z, qa3.w};
    float evB[16] = {qb0.x, qb0.y, qb0.z, qb0.w, qb1.x, qb1.y, qb1.z, qb1.w,
                     qb2.x, qb2.y, qb2.z, qb2.w, qb3.x, qb3.y, qb3.z, qb3.w};

    float lgA[4], lgB[4];
#pragma unroll
    for (int h = 0; h < 4; h++) {
        float sA = 0.f, sB = 0.f;
#pragma unroll
        for (int k = 0; k < 16; k++) {
            float w = we[h * 16 + k];
            sA = fmaf(evA[k], w, sA);
            sB = fmaf(evB[k], w, sB);
        }
        lgA[h] = sA;
        lgB[h] = sB;
    }
    lgA[0] += aA.x + bA.x;  lgA[1] += aA.y + bA.y;
    lgA[2] += aA.z + bA.z;  lgA[3] += aA.w + bA.w;
    lgB[0] += aB.x + bB.x;  lgB[1] += aB.y + bB.y;
    lgB[2] += aB.z + bB.z;  lgB[3] += aB.w + bB.w;
#pragma unroll
    for (int h = 0; h < 4; h++) {
        float vA = (lgA[h] > 0.f) ? lgA[h] : 0.2f * lgA[h];
        float vB = (lgB[h] > 0.f) ? lgB[h] : 0.2f * lgB[h];
        lgA[h] = __expf(vA);
        lgB[h] = __expf(vB);
    }

    // ---- store phase ----
    {
        __half2 x01 = __floats2half2_rn(lgA[0], lgA[1]);
        __half2 x23 = __floats2half2_rn(lgA[2], lgA[3]);
        uint4 rec;
        rec.x = (unsigned)srcA;
        rec.y = *(const unsigned*)&x01;
        rec.z = *(const unsigned*)&x23;
        rec.w = 0u;
        g_csr[ofA + rkA] = rec;
    }
    {
        __half2 x01 = __floats2half2_rn(lgB[0], lgB[1]);
        __half2 x23 = __floats2half2_rn(lgB[2], lgB[3]);
        uint4 rec;
        rec.x = (unsigned)srcB;
        rec.y = *(const unsigned*)&x01;
        rec.z = *(const unsigned*)&x23;
        rec.w = 0u;
        g_csr[ofB + rkB] = rec;
    }
}

// ---------------- aggregation: SINGLE-PASS softmax (numerator & denom together) ------
// out = (sum_e exp_e * h[src_e]) / (sum_e exp_e); division deferred to the end.
__global__ __launch_bounds__(256) void k_agg(const float* __restrict__ bias,
                                             float* __restrict__ out) {
    __shared__ float s_exp[8][32][4];
    __shared__ int   s_src[8][32];

    int warp = threadIdx.x >> 5;
    int lane = threadIdx.x & 31;
    int n = blockIdx.x * 8 + warp;
    if (n >= N_NODES) return;

    int beg = g_off[n];
    int end = g_off[n + 1];
    int myh = lane >> 3;

    float4 acc = {0.f, 0.f, 0.f, 0.f};
    float den = 0.f;
    const __half* hh = g_hh;
    for (int c = beg; c < end; c += 32) {
        int i = c + lane;
        int nb = min(32, end - c);
        if (lane < nb) {
            uint4 r = g_csr[i];
            float2 f01 = __half22float2(*(const __half2*)&r.y);
            float2 f23 = __half22float2(*(const __half2*)&r.z);
            s_src[warp][lane] = (int)r.x;
            s_exp[warp][lane][0] = f01.x;
            s_exp[warp][lane][1] = f01.y;
            s_exp[warp][lane][2] = f23.x;
            s_exp[warp][lane][3] = f23.y;
        }
        __syncwarp();
        int j = 0;
        for (; j + 8 <= nb; j += 8) {
            uint2 rr[8];
            float aa[8];
#pragma unroll
            for (int u = 0; u < 8; u++) {
                int sj = s_src[warp][j + u];
                rr[u] = *(const uint2*)&hh[sj * HD + lane * 4];
                aa[u] = s_exp[warp][j + u][myh];
            }
#pragma unroll
            for (int u = 0; u < 8; u++) {
                float2 f01 = __half22float2(*(const __half2*)&rr[u].x);
                float2 f23 = __half22float2(*(const __half2*)&rr[u].y);
                acc.x = fmaf(aa[u], f01.x, acc.x);
                acc.y = fmaf(aa[u], f01.y, acc.y);
                acc.z = fmaf(aa[u], f23.x, acc.z);
                acc.w = fmaf(aa[u], f23.y, acc.w);
                den += aa[u];
            }
        }
        for (; j < nb; j++) {
            int sj = s_src[warp][j];
            float a = s_exp[warp][j][myh];
            uint2 r = *(const uint2*)&hh[sj * HD + lane * 4];
            float2 f01 = __half22float2(*(const __half2*)&r.x);
            float2 f23 = __half22float2(*(const __half2*)&r.y);
            acc.x = fmaf(a, f01.x, acc.x);
            acc.y = fmaf(a, f01.y, acc.y);
            acc.z = fmaf(a, f23.x, acc.z);
            acc.w = fmaf(a, f23.y, acc.w);
            den += a;
        }
        __syncwarp();
    }

    // normalize by this head's denominator
    float inv = 1.f / (den + 1e-16f);
    acc.x *= inv;
    acc.y *= inv;
    acc.z *= inv;
    acc.w *= inv;

    // reduce over heads (lanes l, l^8, l^16, l^24 hold heads 0..3, same dims)
    acc.x += __shfl_xor_sync(0xffffffffu, acc.x, 8);
    acc.y += __shfl_xor_sync(0xffffffffu, acc.y, 8);
    acc.z += __shfl_xor_sync(0xffffffffu, acc.z, 8);
    acc.w += __shfl_xor_sync(0xffffffffu, acc.w, 8);
    acc.x += __shfl_xor_sync(0xffffffffu, acc.x, 16);
    acc.y += __shfl_xor_sync(0xffffffffu, acc.y, 16);
    acc.z += __shfl_xor_sync(0xffffffffu, acc.z, 16);
    acc.w += __shfl_xor_sync(0xffffffffu, acc.w, 16);

    if (lane < 8) {
        float4 b4 = *(const float4*)&bias[lane * 4];
        float4 o;
        o.x = acc.x * 0.25f + b4.x;
        o.y = acc.y * 0.25f + b4.y;
        o.z = acc.z * 0.25f + b4.z;
        o.w = acc.w * 0.25f + b4.w;
        *(float4*)&out[n * OUT_DIM + lane * 4] = o;
    }
}

// ---------------- launch: 4 kernels; index 3 (k_agg) is the profiled one ----------------
extern "C" void kernel_launch(void* const* d_in, const int* in_sizes, int n_in,
                              void* d_out, int out_size) {
    const float* x    = (const float*)d_in[0];
    const int*   ei   = (const int*)  d_in[1];
    const float* ea   = (const float*)d_in[2];
    const float* Wl   = (const float*)d_in[3];
    const float* as   = (const float*)d_in[4];
    const float* ad   = (const float*)d_in[5];
    const float* bias = (const float*)d_in[6];
    const float* We   = (const float*)d_in[7];
    float* out = (float*)d_out;

    k_hist  <<<(N_EDGES / 8 + 255) / 256, 256>>>(ei, Wl);
    k_sgemm <<<98 + (N_NODES + 127) / 128, 256>>>(x, as, ad);
    k_edge  <<<3125, 256>>>(ei, ea, We);
    k_agg   <<<(N_NODES + 7) / 8, 256>>>(bias, out);
}